// round 2
// baseline (speedup 1.0000x reference)
#include <cuda_runtime.h>
#include <cstdint>

#define NN 100000
#define NE 1600000

// Scratch (device globals; no allocation APIs allowed)
__device__ __align__(16) float g_X[NN * 64];     // node features (post-relu)
__device__ __align__(16) float g_ACC[NN * 64];   // residual + aggregated messages
__device__ __align__(16) float g_D[NN * 128];    // dst-side projections [f|s], bias folded
__device__ __align__(16) float g_S[NN * 128];    // src-side projections [f|s]
__device__ __align__(16) float g_E5[NE * 5];     // relu(edge_attr @ short_w + b)

__device__ __forceinline__ float sigm(float x) {
    return 1.0f / (1.0f + __expf(-x));
}
__device__ __forceinline__ float softplus_f(float x) {
    // stable: max(x,0) + log1p(exp(-|x|))
    return fmaxf(x, 0.0f) + __logf(1.0f + __expf(-fabsf(x)));
}

// ---------------------------------------------------------------------------
// K1: X = relu(h @ lin0_w + lin0_b); ACC = X
// ---------------------------------------------------------------------------
__global__ __launch_bounds__(256) void k_lin0(const float* __restrict__ h,
                                              const float* __restrict__ w,
                                              const float* __restrict__ b) {
    __shared__ float Ws[64 * 64];
    __shared__ float Bs[64];
    __shared__ float Xs[8][64];
    const int t = threadIdx.x;
    for (int i = t; i < 64 * 64; i += 256) Ws[i] = w[i];
    if (t < 64) Bs[t] = b[t];

    const int base = blockIdx.x * 64;
    const int c = t & 63;
    const int r0 = t >> 6;  // 0..3

    for (int j = 0; j < 64; j += 8) {
        __syncthreads();
        for (int i = t; i < 8 * 64; i += 256) {
            int n = base + j + (i >> 6);
            Xs[i >> 6][i & 63] = (n < NN) ? h[(size_t)n * 64 + (i & 63)] : 0.0f;
        }
        __syncthreads();
#pragma unroll
        for (int rr = 0; rr < 2; rr++) {
            int row = r0 + rr * 4;
            int n = base + j + row;
            if (n < NN) {
                float acc = Bs[c];
#pragma unroll
                for (int k = 0; k < 64; k++)
                    acc = fmaf(Xs[row][k], Ws[k * 64 + c], acc);
                float v = fmaxf(acc, 0.0f);
                g_X[(size_t)n * 64 + c] = v;
                g_ACC[(size_t)n * 64 + c] = v;
            }
        }
    }
}

// ---------------------------------------------------------------------------
// K2: E5 = relu(edge_attr @ short_w + short_b), [E,5]@[5,5]
// ---------------------------------------------------------------------------
__global__ __launch_bounds__(256) void k_edgefeat(const float* __restrict__ ea,
                                                  const float* __restrict__ w,
                                                  const float* __restrict__ b) {
    int e = blockIdx.x * 256 + threadIdx.x;
    if (e >= NE) return;
    float a0 = ea[(size_t)e * 5 + 0], a1 = ea[(size_t)e * 5 + 1],
          a2 = ea[(size_t)e * 5 + 2], a3 = ea[(size_t)e * 5 + 3],
          a4 = ea[(size_t)e * 5 + 4];
#pragma unroll
    for (int c = 0; c < 5; c++) {
        float acc = b[c];
        acc = fmaf(a0, w[0 * 5 + c], acc);
        acc = fmaf(a1, w[1 * 5 + c], acc);
        acc = fmaf(a2, w[2 * 5 + c], acc);
        acc = fmaf(a3, w[3 * 5 + c], acc);
        acc = fmaf(a4, w[4 * 5 + c], acc);
        g_E5[(size_t)e * 5 + c] = fmaxf(acc, 0.0f);
    }
}

// ---------------------------------------------------------------------------
// K3: node projections.  grid.y selects half:
//   H=0 -> D[n][128] = [X@Wf[0:64] + bf | X@Ws[0:64] + bs]
//   H=1 -> S[n][128] = [X@Wf[64:128]   | X@Ws[64:128]]
// Register-blocked 128x128 tile, 8x8 per thread.
// ---------------------------------------------------------------------------
__global__ __launch_bounds__(256) void k_proj(const float* __restrict__ wf,
                                              const float* __restrict__ ws,
                                              const float* __restrict__ bf,
                                              const float* __restrict__ bs) {
    __shared__ float Xs[32 * 129];   // [k][node], padded
    __shared__ float Wsm[32 * 128];  // [k][col]
    const int t = threadIdx.x;
    const int tx = t & 15, ty = t >> 4;
    const int H = blockIdx.y;
    const int base = blockIdx.x * 128;

    float acc[8][8];
#pragma unroll
    for (int i = 0; i < 8; i++)
#pragma unroll
        for (int j = 0; j < 8; j++) acc[i][j] = 0.0f;

    for (int ks = 0; ks < 64; ks += 32) {
        __syncthreads();
#pragma unroll
        for (int r = 0; r < 16; r++) {
            int idx = t + 256 * r;   // 0..4095
            int n = idx >> 5;        // 0..127
            int k = idx & 31;
            int gn = base + n;
            float v = (gn < NN) ? g_X[(size_t)gn * 64 + ks + k] : 0.0f;
            Xs[k * 129 + n] = v;
        }
#pragma unroll
        for (int r = 0; r < 16; r++) {
            int idx = t + 256 * r;
            int k = idx >> 7;        // 0..31
            int c = idx & 127;
            int grow = H * 64 + ks + k;
            float v = (c < 64) ? wf[grow * 64 + c] : ws[grow * 64 + (c - 64)];
            Wsm[k * 128 + c] = v;
        }
        __syncthreads();
#pragma unroll
        for (int k = 0; k < 32; k++) {
            float xr[8], wr[8];
#pragma unroll
            for (int i = 0; i < 8; i++) xr[i] = Xs[k * 129 + i * 16 + ty];
#pragma unroll
            for (int j = 0; j < 8; j++) wr[j] = Wsm[k * 128 + j * 16 + tx];
#pragma unroll
            for (int i = 0; i < 8; i++)
#pragma unroll
                for (int j = 0; j < 8; j++)
                    acc[i][j] = fmaf(xr[i], wr[j], acc[i][j]);
        }
    }

    float* out = (H == 0) ? g_D : g_S;
#pragma unroll
    for (int i = 0; i < 8; i++) {
        int n = base + i * 16 + ty;
        if (n >= NN) continue;
#pragma unroll
        for (int j = 0; j < 8; j++) {
            int c = j * 16 + tx;
            float v = acc[i][j];
            if (H == 0) v += (c < 64) ? bf[c] : bs[c - 64];
            out[(size_t)n * 128 + c] = v;
        }
    }
}

// ---------------------------------------------------------------------------
// K4: per-edge gated message + atomic aggregation.
// 16 threads/edge; lane l owns channels [4l, 4l+4) via float4.
// edge_index is INT32 [2, NE] (jax x64 disabled): row 0 = src, row 1 = dst.
// ---------------------------------------------------------------------------
__global__ __launch_bounds__(256) void k_edge(const int* __restrict__ ei,
                                              const float* __restrict__ wef,
                                              const float* __restrict__ wes) {
    __shared__ float4 Wf4[80];  // 5 x 64 floats
    __shared__ float4 Ws4[80];
    const int t = threadIdx.x;
    if (t < 80) {
        const float* p = wef + t * 4;
        Wf4[t] = make_float4(p[0], p[1], p[2], p[3]);
        const float* q = wes + t * 4;
        Ws4[t] = make_float4(q[0], q[1], q[2], q[3]);
    }
    __syncthreads();

    long long gid = (long long)blockIdx.x * 256 + t;
    int e = (int)(gid >> 4);
    if (e >= NE) return;
    int l = (int)(gid & 15);

    int s = ei[e];
    int d = ei[NE + e];
    float e0 = g_E5[(size_t)e * 5 + 0];
    float e1 = g_E5[(size_t)e * 5 + 1];
    float e2 = g_E5[(size_t)e * 5 + 2];
    float e3 = g_E5[(size_t)e * 5 + 3];
    float e4 = g_E5[(size_t)e * 5 + 4];

    const float4* Dp = reinterpret_cast<const float4*>(g_D + (size_t)d * 128);
    const float4* Sp = reinterpret_cast<const float4*>(g_S + (size_t)s * 128);

    float4 zf, zs;
    {
        float4 a = Dp[l], b = Sp[l];
        float4 c0 = Wf4[0 * 16 + l], c1 = Wf4[1 * 16 + l], c2 = Wf4[2 * 16 + l],
               c3 = Wf4[3 * 16 + l], c4 = Wf4[4 * 16 + l];
        zf.x = a.x + b.x + e0 * c0.x + e1 * c1.x + e2 * c2.x + e3 * c3.x + e4 * c4.x;
        zf.y = a.y + b.y + e0 * c0.y + e1 * c1.y + e2 * c2.y + e3 * c3.y + e4 * c4.y;
        zf.z = a.z + b.z + e0 * c0.z + e1 * c1.z + e2 * c2.z + e3 * c3.z + e4 * c4.z;
        zf.w = a.w + b.w + e0 * c0.w + e1 * c1.w + e2 * c2.w + e3 * c3.w + e4 * c4.w;
    }
    {
        float4 a = Dp[16 + l], b = Sp[16 + l];
        float4 c0 = Ws4[0 * 16 + l], c1 = Ws4[1 * 16 + l], c2 = Ws4[2 * 16 + l],
               c3 = Ws4[3 * 16 + l], c4 = Ws4[4 * 16 + l];
        zs.x = a.x + b.x + e0 * c0.x + e1 * c1.x + e2 * c2.x + e3 * c3.x + e4 * c4.x;
        zs.y = a.y + b.y + e0 * c0.y + e1 * c1.y + e2 * c2.y + e3 * c3.y + e4 * c4.y;
        zs.z = a.z + b.z + e0 * c0.z + e1 * c1.z + e2 * c2.z + e3 * c3.z + e4 * c4.z;
        zs.w = a.w + b.w + e0 * c0.w + e1 * c1.w + e2 * c2.w + e3 * c3.w + e4 * c4.w;
    }

    float4 m;
    m.x = sigm(zf.x) * softplus_f(zs.x);
    m.y = sigm(zf.y) * softplus_f(zs.y);
    m.z = sigm(zf.z) * softplus_f(zs.z);
    m.w = sigm(zf.w) * softplus_f(zs.w);

    float* dst = g_ACC + (size_t)d * 64 + 4 * l;
    asm volatile("red.global.add.v4.f32 [%0], {%1, %2, %3, %4};"
                 :: "l"(dst), "f"(m.x), "f"(m.y), "f"(m.z), "f"(m.w)
                 : "memory");
}

// ---------------------------------------------------------------------------
// K5: relu of ACC.  mode 0: X = relu(ACC); ACC = X   mode 1: out = relu(ACC)
// ---------------------------------------------------------------------------
__global__ __launch_bounds__(256) void k_relu(float* __restrict__ out, int final_) {
    int i = blockIdx.x * 256 + threadIdx.x;
    if (i >= NN * 16) return;
    float4* A = reinterpret_cast<float4*>(g_ACC);
    float4 v = A[i];
    v.x = fmaxf(v.x, 0.0f);
    v.y = fmaxf(v.y, 0.0f);
    v.z = fmaxf(v.z, 0.0f);
    v.w = fmaxf(v.w, 0.0f);
    if (final_) {
        reinterpret_cast<float4*>(out)[i] = v;
    } else {
        reinterpret_cast<float4*>(g_X)[i] = v;
        A[i] = v;
    }
}

// ---------------------------------------------------------------------------
// Launch. Input order: h, edge_index, edge_weight, edge_attr, data,
// lin0_w, lin0_b, short_w, short_b, conv_f_w, conv_f_b, conv_s_w, conv_s_b
// ---------------------------------------------------------------------------
extern "C" void kernel_launch(void* const* d_in, const int* in_sizes, int n_in,
                              void* d_out, int out_size) {
    int o = (n_in >= 13) ? 0 : -1;  // tolerate dropped scalar 'data'

    const float* h = (const float*)d_in[0];
    const int* ei = (const int*)d_in[1];      // int32 [2, NE]
    const float* ea = (const float*)d_in[3];
    const float* lin0_w = (const float*)d_in[5 + o];
    const float* lin0_b = (const float*)d_in[6 + o];
    const float* short_w = (const float*)d_in[7 + o];
    const float* short_b = (const float*)d_in[8 + o];
    const float* cfw = (const float*)d_in[9 + o];   // [2,133,64]
    const float* cfb = (const float*)d_in[10 + o];  // [2,64]
    const float* csw = (const float*)d_in[11 + o];
    const float* csb = (const float*)d_in[12 + o];
    float* out = (float*)d_out;

    k_lin0<<<(NN + 63) / 64, 256>>>(h, lin0_w, lin0_b);
    k_edgefeat<<<(NE + 255) / 256, 256>>>(ea, short_w, short_b);

    for (int i = 0; i < 2; i++) {
        const float* wf = cfw + (size_t)i * 133 * 64;
        const float* ws = csw + (size_t)i * 133 * 64;
        dim3 pg((NN + 127) / 128, 2);
        k_proj<<<pg, 256>>>(wf, ws, cfb + i * 64, csb + i * 64);
        k_edge<<<(int)(((long long)NE * 16 + 255) / 256), 256>>>(
            ei, wf + 128 * 64, ws + 128 * 64);
        k_relu<<<(NN * 16 + 255) / 256, 256>>>(out, i == 1 ? 1 : 0);
    }
}

// round 3
// speedup vs baseline: 1.4183x; 1.4183x over previous
#include <cuda_runtime.h>
#include <cstdint>

#define NN 100000
#define NE 1600000

// ---------------- device scratch (no allocation APIs allowed) ----------------
__device__ __align__(16) float g_X[NN * 64];      // node features (post-relu)
__device__ __align__(16) float g_D[NN * 128];     // dst-side proj [f|s], bias folded
__device__ __align__(16) float g_S[NN * 128];     // src-side proj [f|s]
__device__ __align__(16) float g_E5[NE * 5];      // relu(edge_attr@short_w+b), PERMUTED order
__device__ int g_deg[NN];                         // degree / scatter cursor
__device__ int g_off[NN + 1];                     // CSR offsets (by dst)
__device__ int g_srcp[NE];                        // src node id, permuted (sorted by dst)
__device__ int g_rank[NE];                        // edge e -> permuted slot

__device__ __forceinline__ float sigm_t(float x) {
    // sigmoid via HW tanh: 1 MUFU
    float t;
    asm("tanh.approx.f32 %0, %1;" : "=f"(t) : "f"(0.5f * x));
    return fmaf(0.5f, t, 0.5f);
}
__device__ __forceinline__ float softplus_f(float x) {
    return fmaxf(x, 0.0f) + __logf(1.0f + __expf(-fabsf(x)));
}

// ---------------------------------------------------------------------------
// CSR build
// ---------------------------------------------------------------------------
__global__ void k_zero_deg() {
    int i = blockIdx.x * 256 + threadIdx.x;
    if (i < NN) g_deg[i] = 0;
}

__global__ void k_hist(const int* __restrict__ ei) {
    int e = blockIdx.x * 256 + threadIdx.x;
    if (e < NE) atomicAdd(&g_deg[ei[NE + e]], 1);
}

// single-block exclusive scan: 1024 threads, 98 elems/thread
__global__ __launch_bounds__(1024) void k_scan() {
    const int C = 98;
    int t = threadIdx.x;
    int beg = t * C;
    int end = min(beg + C, NN);
    int sum = 0;
    for (int i = beg; i < end; i++) sum += g_deg[i];

    __shared__ int wsum[32];
    int lane = t & 31, wid = t >> 5;
    int v = sum;
#pragma unroll
    for (int o = 1; o < 32; o <<= 1) {
        int u = __shfl_up_sync(0xffffffffu, v, o);
        if (lane >= o) v += u;
    }
    if (lane == 31) wsum[wid] = v;
    __syncthreads();
    if (wid == 0) {
        int w = wsum[lane];
#pragma unroll
        for (int o = 1; o < 32; o <<= 1) {
            int u = __shfl_up_sync(0xffffffffu, w, o);
            if (lane >= o) w += u;
        }
        wsum[lane] = w;
    }
    __syncthreads();
    int excl = v - sum + (wid > 0 ? wsum[wid - 1] : 0);
    int run = excl;
    for (int i = beg; i < end; i++) {
        g_off[i] = run;
        run += g_deg[i];
    }
    if (t == 1023) g_off[NN] = run;
}

__global__ void k_scatter(const int* __restrict__ ei) {
    int e = blockIdx.x * 256 + threadIdx.x;
    if (e >= NE) return;
    int d = ei[NE + e];
    int pos = g_off[d] + atomicAdd(&g_deg[d], 1);
    g_srcp[pos] = ei[e];
    g_rank[e] = pos;
}

// ---------------------------------------------------------------------------
// K1: X = relu(h @ lin0_w + lin0_b)
// ---------------------------------------------------------------------------
__global__ __launch_bounds__(256) void k_lin0(const float* __restrict__ h,
                                              const float* __restrict__ w,
                                              const float* __restrict__ b) {
    __shared__ float Ws[64 * 64];
    __shared__ float Bs[64];
    __shared__ float Xs[8][64];
    const int t = threadIdx.x;
    for (int i = t; i < 64 * 64; i += 256) Ws[i] = w[i];
    if (t < 64) Bs[t] = b[t];

    const int base = blockIdx.x * 64;
    const int c = t & 63;
    const int r0 = t >> 6;

    for (int j = 0; j < 64; j += 8) {
        __syncthreads();
        for (int i = t; i < 8 * 64; i += 256) {
            int n = base + j + (i >> 6);
            Xs[i >> 6][i & 63] = (n < NN) ? h[(size_t)n * 64 + (i & 63)] : 0.0f;
        }
        __syncthreads();
#pragma unroll
        for (int rr = 0; rr < 2; rr++) {
            int row = r0 + rr * 4;
            int n = base + j + row;
            if (n < NN) {
                float acc = Bs[c];
#pragma unroll
                for (int k = 0; k < 64; k++)
                    acc = fmaf(Xs[row][k], Ws[k * 64 + c], acc);
                g_X[(size_t)n * 64 + c] = fmaxf(acc, 0.0f);
            }
        }
    }
}

// ---------------------------------------------------------------------------
// K2: E5 (permuted) = relu(edge_attr @ short_w + short_b)
// ---------------------------------------------------------------------------
__global__ __launch_bounds__(256) void k_edgefeat(const float* __restrict__ ea,
                                                  const float* __restrict__ w,
                                                  const float* __restrict__ b) {
    int e = blockIdx.x * 256 + threadIdx.x;
    if (e >= NE) return;
    float a0 = ea[(size_t)e * 5 + 0], a1 = ea[(size_t)e * 5 + 1],
          a2 = ea[(size_t)e * 5 + 2], a3 = ea[(size_t)e * 5 + 3],
          a4 = ea[(size_t)e * 5 + 4];
    size_t o = (size_t)g_rank[e] * 5;
#pragma unroll
    for (int c = 0; c < 5; c++) {
        float acc = b[c];
        acc = fmaf(a0, w[0 * 5 + c], acc);
        acc = fmaf(a1, w[1 * 5 + c], acc);
        acc = fmaf(a2, w[2 * 5 + c], acc);
        acc = fmaf(a3, w[3 * 5 + c], acc);
        acc = fmaf(a4, w[4 * 5 + c], acc);
        g_E5[o + c] = fmaxf(acc, 0.0f);
    }
}

// ---------------------------------------------------------------------------
// K3: node projections (H=0 -> D with bias, H=1 -> S). 128x128 tile, 8x8/thread.
// ---------------------------------------------------------------------------
__global__ __launch_bounds__(256) void k_proj(const float* __restrict__ wf,
                                              const float* __restrict__ ws,
                                              const float* __restrict__ bf,
                                              const float* __restrict__ bs) {
    __shared__ float Xs[32 * 129];
    __shared__ float Wsm[32 * 128];
    const int t = threadIdx.x;
    const int tx = t & 15, ty = t >> 4;
    const int H = blockIdx.y;
    const int base = blockIdx.x * 128;

    float acc[8][8];
#pragma unroll
    for (int i = 0; i < 8; i++)
#pragma unroll
        for (int j = 0; j < 8; j++) acc[i][j] = 0.0f;

    for (int ks = 0; ks < 64; ks += 32) {
        __syncthreads();
#pragma unroll
        for (int r = 0; r < 16; r++) {
            int idx = t + 256 * r;
            int n = idx >> 5;
            int k = idx & 31;
            int gn = base + n;
            Xs[k * 129 + n] = (gn < NN) ? g_X[(size_t)gn * 64 + ks + k] : 0.0f;
        }
#pragma unroll
        for (int r = 0; r < 16; r++) {
            int idx = t + 256 * r;
            int k = idx >> 7;
            int c = idx & 127;
            int grow = H * 64 + ks + k;
            Wsm[k * 128 + c] = (c < 64) ? wf[grow * 64 + c] : ws[grow * 64 + (c - 64)];
        }
        __syncthreads();
#pragma unroll
        for (int k = 0; k < 32; k++) {
            float xr[8], wr[8];
#pragma unroll
            for (int i = 0; i < 8; i++) xr[i] = Xs[k * 129 + i * 16 + ty];
#pragma unroll
            for (int j = 0; j < 8; j++) wr[j] = Wsm[k * 128 + j * 16 + tx];
#pragma unroll
            for (int i = 0; i < 8; i++)
#pragma unroll
                for (int j = 0; j < 8; j++)
                    acc[i][j] = fmaf(xr[i], wr[j], acc[i][j]);
        }
    }

    float* out = (H == 0) ? g_D : g_S;
#pragma unroll
    for (int i = 0; i < 8; i++) {
        int n = base + i * 16 + ty;
        if (n >= NN) continue;
#pragma unroll
        for (int j = 0; j < 8; j++) {
            int c = j * 16 + tx;
            float v = acc[i][j];
            if (H == 0) v += (c < 64) ? bf[c] : bs[c - 64];
            out[(size_t)n * 128 + c] = v;
        }
    }
}

// ---------------------------------------------------------------------------
// K4: CSR aggregation. One WARP per dst node; lane l owns channels 2l, 2l+1.
// D row loaded once to regs; edge loop: broadcast src/E5, coalesced S float2s;
// register accumulate; fused residual + relu epilogue. NO atomics.
// ---------------------------------------------------------------------------
__global__ __launch_bounds__(256) void k_edge_csr(const float* __restrict__ wef,
                                                  const float* __restrict__ wes,
                                                  float* __restrict__ out,
                                                  int final_) {
    int gw = (blockIdx.x * 256 + threadIdx.x) >> 5;
    int l = threadIdx.x & 31;
    if (gw >= NN) return;
    const int n = gw;

    // per-lane weight columns (channels 2l, 2l+1), rows 0..4 of e-part
    float wf0[5], wf1[5], ws0[5], ws1[5];
#pragma unroll
    for (int k = 0; k < 5; k++) {
        wf0[k] = wef[k * 64 + 2 * l];
        wf1[k] = wef[k * 64 + 2 * l + 1];
        ws0[k] = wes[k * 64 + 2 * l];
        ws1[k] = wes[k * 64 + 2 * l + 1];
    }

    const float2* D2 = reinterpret_cast<const float2*>(g_D + (size_t)n * 128);
    float2 Df = D2[l];       // f-part, channels 2l,2l+1 (bias folded)
    float2 Dsv = D2[32 + l]; // s-part

    float m0 = 0.0f, m1 = 0.0f;
    int beg = g_off[n], end = g_off[n + 1];

#pragma unroll 2
    for (int k = beg; k < end; k++) {
        int s = g_srcp[k];                       // warp-broadcast load
        const float* ep = g_E5 + (size_t)k * 5;  // warp-broadcast loads
        float e0 = ep[0], e1 = ep[1], e2 = ep[2], e3 = ep[3], e4 = ep[4];
        const float2* S2 = reinterpret_cast<const float2*>(g_S + (size_t)s * 128);
        float2 Sf = __ldg(&S2[l]);
        float2 Ssv = __ldg(&S2[32 + l]);

        float zf0 = Df.x + Sf.x;
        zf0 = fmaf(e0, wf0[0], zf0); zf0 = fmaf(e1, wf0[1], zf0);
        zf0 = fmaf(e2, wf0[2], zf0); zf0 = fmaf(e3, wf0[3], zf0);
        zf0 = fmaf(e4, wf0[4], zf0);
        float zf1 = Df.y + Sf.y;
        zf1 = fmaf(e0, wf1[0], zf1); zf1 = fmaf(e1, wf1[1], zf1);
        zf1 = fmaf(e2, wf1[2], zf1); zf1 = fmaf(e3, wf1[3], zf1);
        zf1 = fmaf(e4, wf1[4], zf1);
        float zs0 = Dsv.x + Ssv.x;
        zs0 = fmaf(e0, ws0[0], zs0); zs0 = fmaf(e1, ws0[1], zs0);
        zs0 = fmaf(e2, ws0[2], zs0); zs0 = fmaf(e3, ws0[3], zs0);
        zs0 = fmaf(e4, ws0[4], zs0);
        float zs1 = Dsv.y + Ssv.y;
        zs1 = fmaf(e0, ws1[0], zs1); zs1 = fmaf(e1, ws1[1], zs1);
        zs1 = fmaf(e2, ws1[2], zs1); zs1 = fmaf(e3, ws1[3], zs1);
        zs1 = fmaf(e4, ws1[4], zs1);

        m0 += sigm_t(zf0) * softplus_f(zs0);
        m1 += sigm_t(zf1) * softplus_f(zs1);
    }

    // residual + relu, fused
    float2 x = *reinterpret_cast<const float2*>(g_X + (size_t)n * 64 + 2 * l);
    float r0 = fmaxf(x.x + m0, 0.0f);
    float r1 = fmaxf(x.y + m1, 0.0f);
    float2 r = make_float2(r0, r1);
    if (final_) {
        *reinterpret_cast<float2*>(out + (size_t)n * 64 + 2 * l) = r;
    } else {
        *reinterpret_cast<float2*>(g_X + (size_t)n * 64 + 2 * l) = r;
    }
}

// ---------------------------------------------------------------------------
// Launch. Inputs: h, edge_index, edge_weight, edge_attr, data,
// lin0_w, lin0_b, short_w, short_b, conv_f_w, conv_f_b, conv_s_w, conv_s_b
// ---------------------------------------------------------------------------
extern "C" void kernel_launch(void* const* d_in, const int* in_sizes, int n_in,
                              void* d_out, int out_size) {
    int o = (n_in >= 13) ? 0 : -1;

    const float* h = (const float*)d_in[0];
    const int* ei = (const int*)d_in[1];  // int32 [2, NE]
    const float* ea = (const float*)d_in[3];
    const float* lin0_w = (const float*)d_in[5 + o];
    const float* lin0_b = (const float*)d_in[6 + o];
    const float* short_w = (const float*)d_in[7 + o];
    const float* short_b = (const float*)d_in[8 + o];
    const float* cfw = (const float*)d_in[9 + o];   // [2,133,64]
    const float* cfb = (const float*)d_in[10 + o];  // [2,64]
    const float* csw = (const float*)d_in[11 + o];
    const float* csb = (const float*)d_in[12 + o];
    float* out = (float*)d_out;

    const int NB = (NN + 255) / 256;
    const int EB = (NE + 255) / 256;

    // CSR build (dst-sorted), shared by both convs
    k_zero_deg<<<NB, 256>>>();
    k_hist<<<EB, 256>>>(ei);
    k_scan<<<1, 1024>>>();
    k_zero_deg<<<NB, 256>>>();
    k_scatter<<<EB, 256>>>(ei);

    k_lin0<<<(NN + 63) / 64, 256>>>(h, lin0_w, lin0_b);
    k_edgefeat<<<EB, 256>>>(ea, short_w, short_b);

    for (int i = 0; i < 2; i++) {
        const float* wf = cfw + (size_t)i * 133 * 64;
        const float* ws = csw + (size_t)i * 133 * 64;
        dim3 pg((NN + 127) / 128, 2);
        k_proj<<<pg, 256>>>(wf, ws, cfb + i * 64, csb + i * 64);
        k_edge_csr<<<(NN * 32 + 255) / 256, 256>>>(wf + 128 * 64, ws + 128 * 64,
                                                   out, i == 1 ? 1 : 0);
    }
}